// round 15
// baseline (speedup 1.0000x reference)
#include <cuda_runtime.h>
#include <cuda_fp16.h>
#include <math.h>

#define NN 100000
#define EE 1600000
#define GG 512
#define EPSBN 1e-5f
#define DEG_BLOCKS 1563   // ceil(EE/4 / 256)
#define G1_BLOCKS 391     // ceil(NN / 256)

// ---------------- scratch ----------------
// Invariant: all accumulators below are zero at kernel_launch entry.
// They start zero (static init) and every invocation re-zeros them after last use.
__device__ int   g_degi[NN];
__device__ int   g_off[NN];
__device__ int   g_woff[NN];
__device__ int   g_total;
__device__ float g_dis[NN];
__device__ float g_rs[NN];             // rowsum of normalized adjacency (incl self)
__device__ int2  g_edge[EE];           // (src, w bits) grouped by dst
__device__ float g_hw [NN * 64];       // fp32: aggT1 [N,16] then a3 [N,64]
__device__ __half2 g_h16[NN * 32];     // fp16: hw1 [N,8 h2] then t2 [N,32 h2]
__device__ __half2 g_t16[NN * 8];      // fp16: t1 [N,8 h2]
__device__ float g_pool[GG * 64];
__device__ float g_cnt[GG];
__device__ double g_s1[16], g_q1[16];  // BN1 sum / sumsq
__device__ double g_s2[64], g_q2[64];  // BN2 sum / sumsq

__device__ __forceinline__ void red4(float* p, float a, float b, float c, float d) {
    asm volatile("red.global.add.v4.f32 [%0], {%1,%2,%3,%4};"
                 :: "l"(p), "f"(a), "f"(b), "f"(c), "f"(d) : "memory");
}
__device__ __forceinline__ float getc(const float4& v, int j) {
    return j == 0 ? v.x : j == 1 ? v.y : j == 2 ? v.z : v.w;
}
__device__ __forceinline__ float2 pack4(float a, float b, float c, float d) {
    __half2 h0 = __floats2half2_rn(a, b);
    __half2 h1 = __floats2half2_rn(c, d);
    float2 r;
    r.x = *(float*)&h0;
    r.y = *(float*)&h1;
    return r;
}
__device__ __forceinline__ float4 unpack4(float2 rv) {
    __half2 a = *(__half2*)&rv.x;
    __half2 b = *(__half2*)&rv.y;
    float2 lo = __half22float2(a), hi = __half22float2(b);
    return make_float4(lo.x, lo.y, hi.x, hi.y);
}
__device__ __forceinline__ void fma4(float4& acc, const float4& m, float w) {
    acc.x = fmaf(m.x, w, acc.x); acc.y = fmaf(m.y, w, acc.y);
    acc.z = fmaf(m.z, w, acc.z); acc.w = fmaf(m.w, w, acc.w);
}

// MERGED: degree histogram (blocks [0,DEG_BLOCKS)) + layer-1 GEMM (rest).
__global__ void __launch_bounds__(256) k_deg_gemm1(const int* __restrict__ ei,
                                                   const float* __restrict__ x,
                                                   const float* __restrict__ W1) {
    if (blockIdx.x < DEG_BLOCKS) {
        int t = blockIdx.x * 256 + threadIdx.x;
        if (t < EE / 4) {
            int4 d4 = ((const int4*)(ei + EE))[t];
            atomicAdd(&g_degi[d4.x], 1);
            atomicAdd(&g_degi[d4.y], 1);
            atomicAdd(&g_degi[d4.z], 1);
            atomicAdd(&g_degi[d4.w], 1);
        }
    } else {
        __shared__ float sW[32 * 16];
        int tid = threadIdx.x;
        for (int j = tid; j < 512; j += 256) sW[j] = W1[j];
        __syncthreads();
        int T = (blockIdx.x - DEG_BLOCKS) * 256 + tid;
        if (T >= NN) return;
        int nq = T >> 2, oq = T & 3;
        int i0 = nq * 4;
        const float4* x4 = (const float4*)x;
        const float4* sW4 = (const float4*)sW;
        float4 acc[4];
        #pragma unroll
        for (int j = 0; j < 4; j++) acc[j] = make_float4(0.f, 0.f, 0.f, 0.f);
        #pragma unroll
        for (int kk = 0; kk < 8; kk++) {
            float4 xv[4];
            #pragma unroll
            for (int j = 0; j < 4; j++) xv[j] = x4[(i0 + j) * 8 + kk];
            #pragma unroll
            for (int jj = 0; jj < 4; jj++) {
                int k = kk * 4 + jj;
                float4 wv = sW4[k * 4 + oq];
                #pragma unroll
                for (int j = 0; j < 4; j++) {
                    float xs = getc(xv[j], jj);
                    fma4(acc[j], wv, xs);
                }
            }
        }
        float2* out2 = (float2*)g_h16;
        #pragma unroll
        for (int j = 0; j < 4; j++)
            out2[(i0 + j) * 4 + oq] = pack4(acc[j].x, acc[j].y, acc[j].z, acc[j].w);
    }
}

// block-level exclusive scan of degrees -> CSR offsets; 1 global atomic per block
__global__ void __launch_bounds__(256) k_scan(const int* __restrict__ batch) {
    __shared__ int wsum[8];
    __shared__ int sbase;
    int i = blockIdx.x * 256 + threadIdx.x;
    int lane = threadIdx.x & 31, wid = threadIdx.x >> 5;
    int d = (i < NN) ? g_degi[i] : 0;
    int v = d;
    #pragma unroll
    for (int s = 1; s < 32; s <<= 1) {
        int t = __shfl_up_sync(0xffffffffu, v, s);
        if (lane >= s) v += t;
    }
    if (lane == 31) wsum[wid] = v;
    __syncthreads();
    if (threadIdx.x < 8) {
        int w = wsum[threadIdx.x];
        #pragma unroll
        for (int s = 1; s < 8; s <<= 1) {
            int t = __shfl_up_sync(0xffu, w, s);
            if ((int)threadIdx.x >= s) w += t;
        }
        wsum[threadIdx.x] = w;
    }
    __syncthreads();
    int incl = v + (wid > 0 ? wsum[wid - 1] : 0);
    if (threadIdx.x == 255) sbase = atomicAdd(&g_total, incl);
    __syncthreads();
    if (i < NN) {
        int off = sbase + incl - d;
        g_off[i] = off;
        g_woff[i] = off;
        g_dis[i] = rsqrtf((float)d + 1.f);
        atomicAdd(&g_cnt[batch[i]], 1.f);
    }
}

__global__ void k_fill(const int* __restrict__ ei) {
    int t = blockIdx.x * blockDim.x + threadIdx.x;
    if (t == 0) g_total = 0;          // restore invariant (scan is done)
    if (t >= EE / 4) return;
    int4 s4 = ((const int4*)ei)[t];
    int4 d4 = ((const int4*)(ei + EE))[t];
    #pragma unroll
    for (int k = 0; k < 4; k++) {
        int s = k == 0 ? s4.x : k == 1 ? s4.y : k == 2 ? s4.z : s4.w;
        int d = k == 0 ? d4.x : k == 1 ? d4.y : k == 2 ? d4.z : d4.w;
        float w = g_dis[s] * g_dis[d];
        int p = atomicAdd(&g_woff[d], 1);
        g_edge[p] = make_int2(s, __float_as_int(w));
    }
}

// ---------------- layer-1 aggregate (unroll-8) + bias + tanh + BN1 stats + rowsum ----------------
__global__ void __launch_bounds__(256) k_agg16(const float* __restrict__ b) {
    __shared__ float ss[16], sq[16];
    int tid = threadIdx.x;
    if (tid < 16) { ss[tid] = 0.f; sq[tid] = 0.f; }
    __syncthreads();
    int n = blockIdx.x * 64 + (tid >> 2);
    int q = tid & 3;
    float v[8] = {0.f,0.f,0.f,0.f,0.f,0.f,0.f,0.f};
    if (n < NN) {
        const float2* h2 = (const float2*)g_h16;
        float d = g_dis[n];
        float d2 = d * d;
        float ws = d2;
        float4 hv = unpack4(h2[n * 4 + q]);
        float4 acc = make_float4(hv.x * d2, hv.y * d2, hv.z * d2, hv.w * d2);
        int j = g_off[n], end = j + g_degi[n];
        for (; j + 8 <= end; j += 8) {
            int2 e[8];
            #pragma unroll
            for (int u = 0; u < 8; u++) e[u] = g_edge[j + u];
            float2 m[8];
            #pragma unroll
            for (int u = 0; u < 8; u++) m[u] = h2[e[u].x * 4 + q];
            #pragma unroll
            for (int u = 0; u < 8; u++) {
                float w = __int_as_float(e[u].y);
                ws += w;
                fma4(acc, unpack4(m[u]), w);
            }
        }
        for (; j < end; j++) {
            int2 e = g_edge[j];
            float w = __int_as_float(e.y);
            float4 m = unpack4(h2[e.x * 4 + q]);
            ws += w;
            fma4(acc, m, w);
        }
        if (q == 0) g_rs[n] = ws;
        float t0 = tanhf(acc.x + b[q * 4 + 0]);
        float t1 = tanhf(acc.y + b[q * 4 + 1]);
        float t2 = tanhf(acc.z + b[q * 4 + 2]);
        float t3 = tanhf(acc.w + b[q * 4 + 3]);
        ((float2*)g_t16)[n * 4 + q] = pack4(t0, t1, t2, t3);
        v[0] = t0; v[1] = t1; v[2] = t2; v[3] = t3;
        v[4] = t0 * t0; v[5] = t1 * t1; v[6] = t2 * t2; v[7] = t3 * t3;
    }
    #pragma unroll
    for (int dstep = 4; dstep <= 16; dstep <<= 1)
        #pragma unroll
        for (int k = 0; k < 8; k++) v[k] += __shfl_xor_sync(0xffffffffu, v[k], dstep);
    int lane = tid & 31;
    if (lane < 4) {
        #pragma unroll
        for (int k = 0; k < 4; k++) {
            atomicAdd(&ss[lane * 4 + k], v[k]);
            atomicAdd(&sq[lane * 4 + k], v[4 + k]);
        }
    }
    __syncthreads();
    if (tid < 16) {
        atomicAdd(&g_s1[tid], (double)ss[tid]);
        atomicAdd(&g_q1[tid], (double)sq[tid]);
    }
}

// ---------------- pure 16-ch aggregate of t1 (fp16, unroll-8) -> aggT1 fp32 ----------------
__global__ void __launch_bounds__(256) k_agg16b() {
    int tid = threadIdx.x;
    int n = blockIdx.x * 64 + (tid >> 2);
    int q = tid & 3;
    if (n >= NN) return;
    const float2* t2p = (const float2*)g_t16;
    float d = g_dis[n];
    float d2 = d * d;
    float4 hv = unpack4(t2p[n * 4 + q]);
    float4 acc = make_float4(hv.x * d2, hv.y * d2, hv.z * d2, hv.w * d2);
    int j = g_off[n], end = j + g_degi[n];
    for (; j + 8 <= end; j += 8) {
        int2 e[8];
        #pragma unroll
        for (int u = 0; u < 8; u++) e[u] = g_edge[j + u];
        float2 m[8];
        #pragma unroll
        for (int u = 0; u < 8; u++) m[u] = t2p[e[u].x * 4 + q];
        #pragma unroll
        for (int u = 0; u < 8; u++) fma4(acc, unpack4(m[u]), __int_as_float(e[u].y));
    }
    for (; j < end; j++) {
        int2 e = g_edge[j];
        float4 m = unpack4(t2p[e.x * 4 + q]);
        fma4(acc, m, __int_as_float(e.y));
    }
    ((float4*)g_hw)[n * 4 + q] = acc;
}

// ---------------- layer 2 GEMM (BN1 folded across agg) + tanh + BN2 stats -> t2 fp16 ----------------
__global__ void __launch_bounds__(128) k_gemm2(const float* __restrict__ W2,
                                               const float* __restrict__ g1,
                                               const float* __restrict__ be1,
                                               const float* __restrict__ b2) {
    __shared__ float sS[16], sC[16], sWp[1024], sCB[64], sB[64];
    __shared__ float ss[64], sq[64];
    int tid = threadIdx.x;
    if (tid < 16) {
        float m = (float)(g_s1[tid] / (double)NN);
        float vv = (float)(g_q1[tid] / (double)NN) - m * m;
        float s = g1[tid] * rsqrtf(vv + EPSBN);
        sS[tid] = s;
        sC[tid] = be1[tid] - m * s;
    }
    if (tid < 64) { ss[tid] = 0.f; sq[tid] = 0.f; sB[tid] = b2[tid]; }
    __syncthreads();
    for (int j = tid; j < 1024; j += blockDim.x) sWp[j] = W2[j] * sS[j >> 6];
    if (tid < 64) {
        float cb = 0.f;
        #pragma unroll
        for (int k = 0; k < 16; k++) cb += sC[k] * W2[k * 64 + tid];
        sCB[tid] = cb;
    }
    __syncthreads();
    int T = blockIdx.x * blockDim.x + tid;
    int nq = T >> 2, oq = T & 3;
    int i0 = nq * 4;
    bool valid = (T < NN);
    float st[16], sqv[16];
    #pragma unroll
    for (int k = 0; k < 16; k++) { st[k] = 0.f; sqv[k] = 0.f; }
    if (valid) {
        const float4* t4 = (const float4*)g_hw;   // aggT1 [N,16] fp32
        const float4* sWp4 = (const float4*)sWp;
        float4 acc[4][4];
        #pragma unroll
        for (int j = 0; j < 4; j++)
            #pragma unroll
            for (int u = 0; u < 4; u++) acc[j][u] = make_float4(0.f, 0.f, 0.f, 0.f);
        #pragma unroll
        for (int kk = 0; kk < 4; kk++) {
            float4 tv[4];
            #pragma unroll
            for (int j = 0; j < 4; j++) tv[j] = t4[(i0 + j) * 4 + kk];
            #pragma unroll
            for (int jj = 0; jj < 4; jj++) {
                int k = kk * 4 + jj;
                float4 wv[4];
                #pragma unroll
                for (int u = 0; u < 4; u++) wv[u] = sWp4[k * 16 + oq * 4 + u];
                #pragma unroll
                for (int j = 0; j < 4; j++) {
                    float xs = getc(tv[j], jj);
                    #pragma unroll
                    for (int u = 0; u < 4; u++) fma4(acc[j][u], wv[u], xs);
                }
            }
        }
        const float4* sCB4 = (const float4*)sCB;
        const float4* sB4 = (const float4*)sB;
        float2* out2 = (float2*)g_h16;            // t2 fp16 [N,16 float2]
        #pragma unroll
        for (int j = 0; j < 4; j++) {
            int i = i0 + j;
            float rs = g_rs[i];
            #pragma unroll
            for (int u = 0; u < 4; u++) {
                float4 cb = sCB4[oq * 4 + u];
                float4 bb = sB4[oq * 4 + u];
                float t0 = tanhf(fmaf(rs, cb.x, acc[j][u].x + bb.x));
                float t1 = tanhf(fmaf(rs, cb.y, acc[j][u].y + bb.y));
                float t2 = tanhf(fmaf(rs, cb.z, acc[j][u].z + bb.z));
                float t3 = tanhf(fmaf(rs, cb.w, acc[j][u].w + bb.w));
                out2[i * 16 + oq * 4 + u] = pack4(t0, t1, t2, t3);
                st[u * 4 + 0] += t0; sqv[u * 4 + 0] += t0 * t0;
                st[u * 4 + 1] += t1; sqv[u * 4 + 1] += t1 * t1;
                st[u * 4 + 2] += t2; sqv[u * 4 + 2] += t2 * t2;
                st[u * 4 + 3] += t3; sqv[u * 4 + 3] += t3 * t3;
            }
        }
    }
    #pragma unroll
    for (int dstep = 4; dstep <= 16; dstep <<= 1)
        #pragma unroll
        for (int k = 0; k < 16; k++) {
            st[k]  += __shfl_xor_sync(0xffffffffu, st[k],  dstep);
            sqv[k] += __shfl_xor_sync(0xffffffffu, sqv[k], dstep);
        }
    int lane = tid & 31;
    if (lane < 4) {
        #pragma unroll
        for (int k = 0; k < 16; k++) {
            atomicAdd(&ss[lane * 16 + k], st[k]);
            atomicAdd(&sq[lane * 16 + k], sqv[k]);
        }
    }
    __syncthreads();
    if (tid < 64) {
        atomicAdd(&g_s2[tid], (double)ss[tid]);
        atomicAdd(&g_q2[tid], (double)sq[tid]);
    }
}

// ---------------- 64-ch aggregate of t2 (warp-per-node, unroll-8) -> a3 fp32 ----------------
__global__ void __launch_bounds__(256) k_agg64() {
    int n = (blockIdx.x * 256 + threadIdx.x) >> 5;
    int lane = threadIdx.x & 31;
    if (n >= NN) return;
    const __half2* t2p = g_h16;
    float d = g_dis[n];
    float d2 = d * d;
    float2 h = __half22float2(t2p[n * 32 + lane]);
    float2 acc = make_float2(h.x * d2, h.y * d2);
    int j = g_off[n], end = j + g_degi[n];
    for (; j + 8 <= end; j += 8) {
        int2 e[8];
        #pragma unroll
        for (int u = 0; u < 8; u++) e[u] = g_edge[j + u];
        __half2 m[8];
        #pragma unroll
        for (int u = 0; u < 8; u++) m[u] = t2p[e[u].x * 32 + lane];
        #pragma unroll
        for (int u = 0; u < 8; u++) {
            float w = __int_as_float(e[u].y);
            float2 mf = __half22float2(m[u]);
            acc.x = fmaf(mf.x, w, acc.x); acc.y = fmaf(mf.y, w, acc.y);
        }
    }
    for (; j < end; j++) {
        int2 e = g_edge[j];
        float w = __int_as_float(e.y);
        float2 m = __half22float2(t2p[e.x * 32 + lane]);
        acc.x = fmaf(m.x, w, acc.x); acc.y = fmaf(m.y, w, acc.y);
    }
    ((float2*)g_hw)[n * 32 + lane] = acc;
}

// ---------------- layer 3 GEMM (BN2 folded across agg) + tanh + pool scatter ----------------
// Also restores g_degi = 0 (its last reader, k_agg64, has completed).
__global__ void __launch_bounds__(128) k_gemm3(const float* __restrict__ W3,
                                               const float* __restrict__ g2,
                                               const float* __restrict__ be2,
                                               const float* __restrict__ b3,
                                               const int* __restrict__ batch) {
    __shared__ float sS[64], sC[64], sWp[4096], sCB[64], sB[64];
    int tid = threadIdx.x;
    int T = blockIdx.x * blockDim.x + tid;
    if (T < NN) g_degi[T] = 0;        // restore invariant
    if (tid < 64) {
        float m = (float)(g_s2[tid] / (double)NN);
        float vv = (float)(g_q2[tid] / (double)NN) - m * m;
        float s = g2[tid] * rsqrtf(vv + EPSBN);
        sS[tid] = s;
        sC[tid] = be2[tid] - m * s;
        sB[tid] = b3[tid];
    }
    __syncthreads();
    for (int j = tid; j < 4096; j += blockDim.x) sWp[j] = W3[j] * sS[j >> 6];
    if (tid < 64) {
        float cb = 0.f;
        #pragma unroll
        for (int k = 0; k < 64; k++) cb += sC[k] * W3[k * 64 + tid];
        sCB[tid] = cb;
    }
    __syncthreads();
    if (T >= NN) return;
    int nq = T >> 2, oq = T & 3;
    int i0 = nq * 4;
    const float4* t4 = (const float4*)g_hw;     // a3 [N,64] fp32
    const float4* sWp4 = (const float4*)sWp;
    float4 acc[4][4];
    #pragma unroll
    for (int j = 0; j < 4; j++)
        #pragma unroll
        for (int u = 0; u < 4; u++) acc[j][u] = make_float4(0.f, 0.f, 0.f, 0.f);
    for (int kk = 0; kk < 16; kk++) {
        float4 tv[4];
        #pragma unroll
        for (int j = 0; j < 4; j++) tv[j] = t4[(i0 + j) * 16 + kk];
        #pragma unroll
        for (int jj = 0; jj < 4; jj++) {
            int k = kk * 4 + jj;
            float4 wv[4];
            #pragma unroll
            for (int u = 0; u < 4; u++) wv[u] = sWp4[k * 16 + oq * 4 + u];
            #pragma unroll
            for (int j = 0; j < 4; j++) {
                float xs = getc(tv[j], jj);
                #pragma unroll
                for (int u = 0; u < 4; u++) fma4(acc[j][u], wv[u], xs);
            }
        }
    }
    const float4* sCB4 = (const float4*)sCB;
    const float4* sB4 = (const float4*)sB;
    #pragma unroll
    for (int j = 0; j < 4; j++) {
        int i = i0 + j;
        float rs = g_rs[i];
        int gidx = batch[i];
        #pragma unroll
        for (int u = 0; u < 4; u++) {
            float4 cb = sCB4[oq * 4 + u];
            float4 bb = sB4[oq * 4 + u];
            float t0 = tanhf(fmaf(rs, cb.x, acc[j][u].x + bb.x));
            float t1 = tanhf(fmaf(rs, cb.y, acc[j][u].y + bb.y));
            float t2 = tanhf(fmaf(rs, cb.z, acc[j][u].z + bb.z));
            float t3 = tanhf(fmaf(rs, cb.w, acc[j][u].w + bb.w));
            red4(&g_pool[gidx * 64 + oq * 16 + u * 4], t0, t1, t2, t3);
        }
    }
}

// ---------------- head + restore accumulators to zero ----------------
__global__ void k_final(const float* __restrict__ Wc, const float* __restrict__ bc,
                        float* __restrict__ out) {
    __shared__ float sW[64];
    int g = threadIdx.x;
    if (g < 64) sW[g] = Wc[g];
    __syncthreads();
    float result = 0.f;
    if (g < GG) {
        float cnt = fmaxf(g_cnt[g], 1.f);
        float acc = 0.f;
        #pragma unroll
        for (int c = 0; c < 64; c++) acc += g_pool[g * 64 + c] * sW[c];
        result = acc / cnt + bc[0];
    }
    __syncthreads();                  // all reads of pool/cnt/stats done
    if (g < GG) out[g] = result;
    // restore invariant: zero accumulators for the next invocation
    float4* p4 = (float4*)g_pool;
    for (int i = g; i < GG * 16; i += 512)
        p4[i] = make_float4(0.f, 0.f, 0.f, 0.f);
    if (g < GG) g_cnt[g] = 0.f;
    if (g < 16) { g_s1[g] = 0.0; g_q1[g] = 0.0; }
    if (g < 64) { g_s2[g] = 0.0; g_q2[g] = 0.0; }
}

// ---------------- launch ----------------
extern "C" void kernel_launch(void* const* d_in, const int* in_sizes, int n_in,
                              void* d_out, int out_size) {
    const float* x    = (const float*)d_in[0];
    const int*   ei   = (const int*)d_in[1];
    const int*   batch= (const int*)d_in[2];
    const float* W1   = (const float*)d_in[3];
    const float* b1   = (const float*)d_in[4];
    const float* g1   = (const float*)d_in[5];
    const float* be1  = (const float*)d_in[6];
    const float* W2   = (const float*)d_in[7];
    const float* b2   = (const float*)d_in[8];
    const float* g2   = (const float*)d_in[9];
    const float* be2  = (const float*)d_in[10];
    const float* W3   = (const float*)d_in[11];
    const float* b3   = (const float*)d_in[12];
    const float* Wc   = (const float*)d_in[13];
    const float* bc   = (const float*)d_in[14];
    float* out = (float*)d_out;

    k_deg_gemm1 <<<DEG_BLOCKS + G1_BLOCKS, 256>>>(ei, x, W1);
    k_scan      <<<(NN + 255) / 256, 256>>>(batch);
    k_fill      <<<(EE / 4 + 255) / 256, 256>>>(ei);

    k_agg16     <<<(NN + 63) / 64, 256>>>(b1);

    k_agg16b    <<<(NN + 63) / 64, 256>>>();
    k_gemm2     <<<(NN + 127) / 128, 128>>>(W2, g1, be1, b2);

    k_agg64     <<<(NN * 32 + 255) / 256, 256>>>();
    k_gemm3     <<<(NN + 127) / 128, 128>>>(W3, g2, be2, b3, batch);

    k_final     <<<1, 512>>>(Wc, bc, out);
}

// round 16
// speedup vs baseline: 1.0231x; 1.0231x over previous
#include <cuda_runtime.h>
#include <cuda_fp16.h>
#include <math.h>

#define NN 100000
#define EE 1600000
#define GG 512
#define EPSBN 1e-5f
#define FILL_BLOCKS 1563  // ceil(EE/4 / 256)
#define G1_BLOCKS 391     // ceil(NN / 256)

// ---------------- scratch ----------------
// Invariant: accumulators are zero at kernel_launch entry (static init +
// each invocation re-zeros them after last use).
__device__ int   g_degi[NN];
__device__ int   g_off[NN];
__device__ int   g_total;
__device__ float g_dis[NN];
__device__ float g_rs[NN];             // rowsum of normalized adjacency (incl self)
__device__ int   g_rank[EE];           // edge rank within its dst group
__device__ int   g_esrc[EE];           // src index, grouped by dst (4 B edges)
__device__ float g_hw [NN * 64];       // fp32: aggT1 [N,16] then a3 [N,64]
__device__ __half2 g_h16[NN * 32];     // fp16 pre-scaled: hw1*dis then t2*dis
__device__ __half2 g_t16[NN * 8];      // fp16 pre-scaled: t1*dis
__device__ float g_pool[GG * 64];
__device__ float g_cnt[GG];
__device__ double g_s1[16], g_q1[16];  // BN1 sum / sumsq
__device__ double g_s2[64], g_q2[64];  // BN2 sum / sumsq

__device__ __forceinline__ void red4(float* p, float a, float b, float c, float d) {
    asm volatile("red.global.add.v4.f32 [%0], {%1,%2,%3,%4};"
                 :: "l"(p), "f"(a), "f"(b), "f"(c), "f"(d) : "memory");
}
__device__ __forceinline__ float getc(const float4& v, int j) {
    return j == 0 ? v.x : j == 1 ? v.y : j == 2 ? v.z : v.w;
}
__device__ __forceinline__ float2 pack4(float a, float b, float c, float d) {
    __half2 h0 = __floats2half2_rn(a, b);
    __half2 h1 = __floats2half2_rn(c, d);
    float2 r;
    r.x = *(float*)&h0;
    r.y = *(float*)&h1;
    return r;
}
__device__ __forceinline__ float4 unpack4(float2 rv) {
    __half2 a = *(__half2*)&rv.x;
    __half2 b = *(__half2*)&rv.y;
    float2 lo = __half22float2(a), hi = __half22float2(b);
    return make_float4(lo.x, lo.y, hi.x, hi.y);
}
__device__ __forceinline__ void add4(float4& acc, const float4& m) {
    acc.x += m.x; acc.y += m.y; acc.z += m.z; acc.w += m.w;
}
__device__ __forceinline__ void fma4(float4& acc, const float4& m, float w) {
    acc.x = fmaf(m.x, w, acc.x); acc.y = fmaf(m.y, w, acc.y);
    acc.z = fmaf(m.z, w, acc.z); acc.w = fmaf(m.w, w, acc.w);
}

// ---------------- degree histogram; returned old value = edge's rank ----------------
__global__ void k_deg(const int* __restrict__ ei) {
    int t = blockIdx.x * blockDim.x + threadIdx.x;
    if (t < EE / 4) {
        int4 d4 = ((const int4*)(ei + EE))[t];
        int4 r4;
        r4.x = atomicAdd(&g_degi[d4.x], 1);
        r4.y = atomicAdd(&g_degi[d4.y], 1);
        r4.z = atomicAdd(&g_degi[d4.z], 1);
        r4.w = atomicAdd(&g_degi[d4.w], 1);
        ((int4*)g_rank)[t] = r4;
    }
}

// block-level exclusive scan of degrees -> CSR offsets; 1 global atomic per block
__global__ void __launch_bounds__(256) k_scan(const int* __restrict__ batch) {
    __shared__ int wsum[8];
    __shared__ int sbase;
    int i = blockIdx.x * 256 + threadIdx.x;
    int lane = threadIdx.x & 31, wid = threadIdx.x >> 5;
    int d = (i < NN) ? g_degi[i] : 0;
    int v = d;
    #pragma unroll
    for (int s = 1; s < 32; s <<= 1) {
        int t = __shfl_up_sync(0xffffffffu, v, s);
        if (lane >= s) v += t;
    }
    if (lane == 31) wsum[wid] = v;
    __syncthreads();
    if (threadIdx.x < 8) {
        int w = wsum[threadIdx.x];
        #pragma unroll
        for (int s = 1; s < 8; s <<= 1) {
            int t = __shfl_up_sync(0xffu, w, s);
            if ((int)threadIdx.x >= s) w += t;
        }
        wsum[threadIdx.x] = w;
    }
    __syncthreads();
    int incl = v + (wid > 0 ? wsum[wid - 1] : 0);
    if (threadIdx.x == 255) sbase = atomicAdd(&g_total, incl);
    __syncthreads();
    if (i < NN) {
        g_off[i] = sbase + incl - d;
        g_dis[i] = rsqrtf((float)d + 1.f);
        atomicAdd(&g_cnt[batch[i]], 1.f);
    }
}

// MERGED: atomic-free CSR fill (blocks [0,FILL_BLOCKS)) + layer-1 GEMM (rest).
// Both need only k_scan's outputs; they overlap in one launch.
__global__ void __launch_bounds__(256) k_fill_gemm1(const int* __restrict__ ei,
                                                    const float* __restrict__ x,
                                                    const float* __restrict__ W1) {
    if (blockIdx.x < FILL_BLOCKS) {
        int t = blockIdx.x * 256 + threadIdx.x;
        if (t == 0) g_total = 0;      // restore invariant (scan done)
        if (t >= EE / 4) return;
        int4 s4 = ((const int4*)ei)[t];
        int4 d4 = ((const int4*)(ei + EE))[t];
        int4 r4 = ((const int4*)g_rank)[t];
        g_esrc[g_off[d4.x] + r4.x] = s4.x;
        g_esrc[g_off[d4.y] + r4.y] = s4.y;
        g_esrc[g_off[d4.z] + r4.z] = s4.z;
        g_esrc[g_off[d4.w] + r4.w] = s4.w;
    } else {
        __shared__ float sW[32 * 16];
        int tid = threadIdx.x;
        for (int j = tid; j < 512; j += 256) sW[j] = W1[j];
        __syncthreads();
        int T = (blockIdx.x - FILL_BLOCKS) * 256 + tid;
        if (T >= NN) return;
        int nq = T >> 2, oq = T & 3;
        int i0 = nq * 4;
        const float4* x4 = (const float4*)x;
        const float4* sW4 = (const float4*)sW;
        float4 acc[4];
        #pragma unroll
        for (int j = 0; j < 4; j++) acc[j] = make_float4(0.f, 0.f, 0.f, 0.f);
        #pragma unroll
        for (int kk = 0; kk < 8; kk++) {
            float4 xv[4];
            #pragma unroll
            for (int j = 0; j < 4; j++) xv[j] = x4[(i0 + j) * 8 + kk];
            #pragma unroll
            for (int jj = 0; jj < 4; jj++) {
                int k = kk * 4 + jj;
                float4 wv = sW4[k * 4 + oq];
                #pragma unroll
                for (int j = 0; j < 4; j++) {
                    float xs = getc(xv[j], jj);
                    fma4(acc[j], wv, xs);
                }
            }
        }
        float2* out2 = (float2*)g_h16;
        #pragma unroll
        for (int j = 0; j < 4; j++) {
            float dn = g_dis[i0 + j];   // pre-scale by dis[src]
            out2[(i0 + j) * 4 + oq] =
                pack4(acc[j].x * dn, acc[j].y * dn, acc[j].z * dn, acc[j].w * dn);
        }
    }
}

// ---------------- layer-1 aggregate (pure sum) + bias + tanh + BN1 stats + rowsum ----------------
__global__ void __launch_bounds__(256) k_agg16(const float* __restrict__ b) {
    __shared__ float ss[16], sq[16];
    int tid = threadIdx.x;
    if (tid < 16) { ss[tid] = 0.f; sq[tid] = 0.f; }
    __syncthreads();
    int n = blockIdx.x * 64 + (tid >> 2);
    int q = tid & 3;
    float v[8] = {0.f,0.f,0.f,0.f,0.f,0.f,0.f,0.f};
    if (n < NN) {
        const float2* h2 = (const float2*)g_h16;
        float dn = g_dis[n];
        float sd = dn;                      // dis[n] + sum dis[s]
        float4 acc = unpack4(h2[n * 4 + q]);// self term (pre-scaled)
        int j = g_off[n], end = j + g_degi[n];
        for (; j + 8 <= end; j += 8) {
            int e[8];
            #pragma unroll
            for (int u = 0; u < 8; u++) e[u] = g_esrc[j + u];
            float2 m[8];
            #pragma unroll
            for (int u = 0; u < 8; u++) m[u] = h2[e[u] * 4 + q];
            if (q == 0) {
                #pragma unroll
                for (int u = 0; u < 8; u++) sd += g_dis[e[u]];
            }
            #pragma unroll
            for (int u = 0; u < 8; u++) add4(acc, unpack4(m[u]));
        }
        for (; j < end; j++) {
            int e = g_esrc[j];
            if (q == 0) sd += g_dis[e];
            add4(acc, unpack4(h2[e * 4 + q]));
        }
        if (q == 0) g_rs[n] = dn * sd;
        float t0 = tanhf(fmaf(dn, acc.x, b[q * 4 + 0]));
        float t1 = tanhf(fmaf(dn, acc.y, b[q * 4 + 1]));
        float t2 = tanhf(fmaf(dn, acc.z, b[q * 4 + 2]));
        float t3 = tanhf(fmaf(dn, acc.w, b[q * 4 + 3]));
        ((float2*)g_t16)[n * 4 + q] = pack4(t0 * dn, t1 * dn, t2 * dn, t3 * dn);
        v[0] = t0; v[1] = t1; v[2] = t2; v[3] = t3;
        v[4] = t0 * t0; v[5] = t1 * t1; v[6] = t2 * t2; v[7] = t3 * t3;
    }
    #pragma unroll
    for (int dstep = 4; dstep <= 16; dstep <<= 1)
        #pragma unroll
        for (int k = 0; k < 8; k++) v[k] += __shfl_xor_sync(0xffffffffu, v[k], dstep);
    int lane = tid & 31;
    if (lane < 4) {
        #pragma unroll
        for (int k = 0; k < 4; k++) {
            atomicAdd(&ss[lane * 4 + k], v[k]);
            atomicAdd(&sq[lane * 4 + k], v[4 + k]);
        }
    }
    __syncthreads();
    if (tid < 16) {
        atomicAdd(&g_s1[tid], (double)ss[tid]);
        atomicAdd(&g_q1[tid], (double)sq[tid]);
    }
}

// ---------------- pure 16-ch aggregate of t1*dis -> aggT1 = Â t1 (fp32) ----------------
__global__ void __launch_bounds__(256) k_agg16b() {
    int tid = threadIdx.x;
    int n = blockIdx.x * 64 + (tid >> 2);
    int q = tid & 3;
    if (n >= NN) return;
    const float2* t2p = (const float2*)g_t16;
    float dn = g_dis[n];
    float4 acc = unpack4(t2p[n * 4 + q]);
    int j = g_off[n], end = j + g_degi[n];
    for (; j + 8 <= end; j += 8) {
        int e[8];
        #pragma unroll
        for (int u = 0; u < 8; u++) e[u] = g_esrc[j + u];
        float2 m[8];
        #pragma unroll
        for (int u = 0; u < 8; u++) m[u] = t2p[e[u] * 4 + q];
        #pragma unroll
        for (int u = 0; u < 8; u++) add4(acc, unpack4(m[u]));
    }
    for (; j < end; j++) add4(acc, unpack4(t2p[g_esrc[j] * 4 + q]));
    ((float4*)g_hw)[n * 4 + q] =
        make_float4(acc.x * dn, acc.y * dn, acc.z * dn, acc.w * dn);
}

// ---------------- layer 2 GEMM (BN1 folded across agg) + tanh + BN2 stats -> t2*dis fp16 ----------------
__global__ void __launch_bounds__(128) k_gemm2(const float* __restrict__ W2,
                                               const float* __restrict__ g1,
                                               const float* __restrict__ be1,
                                               const float* __restrict__ b2) {
    __shared__ float sS[16], sC[16], sWp[1024], sCB[64], sB[64];
    __shared__ float ss[64], sq[64];
    int tid = threadIdx.x;
    if (tid < 16) {
        float m = (float)(g_s1[tid] / (double)NN);
        float vv = (float)(g_q1[tid] / (double)NN) - m * m;
        float s = g1[tid] * rsqrtf(vv + EPSBN);
        sS[tid] = s;
        sC[tid] = be1[tid] - m * s;
    }
    if (tid < 64) { ss[tid] = 0.f; sq[tid] = 0.f; sB[tid] = b2[tid]; }
    __syncthreads();
    for (int j = tid; j < 1024; j += blockDim.x) sWp[j] = W2[j] * sS[j >> 6];
    if (tid < 64) {
        float cb = 0.f;
        #pragma unroll
        for (int k = 0; k < 16; k++) cb += sC[k] * W2[k * 64 + tid];
        sCB[tid] = cb;
    }
    __syncthreads();
    int T = blockIdx.x * blockDim.x + tid;
    int nq = T >> 2, oq = T & 3;
    int i0 = nq * 4;
    bool valid = (T < NN);
    float st[16], sqv[16];
    #pragma unroll
    for (int k = 0; k < 16; k++) { st[k] = 0.f; sqv[k] = 0.f; }
    if (valid) {
        const float4* t4 = (const float4*)g_hw;   // aggT1 [N,16] fp32
        const float4* sWp4 = (const float4*)sWp;
        float4 acc[4][4];
        #pragma unroll
        for (int j = 0; j < 4; j++)
            #pragma unroll
            for (int u = 0; u < 4; u++) acc[j][u] = make_float4(0.f, 0.f, 0.f, 0.f);
        #pragma unroll
        for (int kk = 0; kk < 4; kk++) {
            float4 tv[4];
            #pragma unroll
            for (int j = 0; j < 4; j++) tv[j] = t4[(i0 + j) * 4 + kk];
            #pragma unroll
            for (int jj = 0; jj < 4; jj++) {
                int k = kk * 4 + jj;
                float4 wv[4];
                #pragma unroll
                for (int u = 0; u < 4; u++) wv[u] = sWp4[k * 16 + oq * 4 + u];
                #pragma unroll
                for (int j = 0; j < 4; j++) {
                    float xs = getc(tv[j], jj);
                    #pragma unroll
                    for (int u = 0; u < 4; u++) fma4(acc[j][u], wv[u], xs);
                }
            }
        }
        const float4* sCB4 = (const float4*)sCB;
        const float4* sB4 = (const float4*)sB;
        float2* out2 = (float2*)g_h16;            // t2*dis fp16 [N,16 float2]
        #pragma unroll
        for (int j = 0; j < 4; j++) {
            int i = i0 + j;
            float rs = g_rs[i];
            float dn = g_dis[i];
            #pragma unroll
            for (int u = 0; u < 4; u++) {
                float4 cb = sCB4[oq * 4 + u];
                float4 bb = sB4[oq * 4 + u];
                float t0 = tanhf(fmaf(rs, cb.x, acc[j][u].x + bb.x));
                float t1 = tanhf(fmaf(rs, cb.y, acc[j][u].y + bb.y));
                float t2 = tanhf(fmaf(rs, cb.z, acc[j][u].z + bb.z));
                float t3 = tanhf(fmaf(rs, cb.w, acc[j][u].w + bb.w));
                out2[i * 16 + oq * 4 + u] = pack4(t0 * dn, t1 * dn, t2 * dn, t3 * dn);
                st[u * 4 + 0] += t0; sqv[u * 4 + 0] += t0 * t0;
                st[u * 4 + 1] += t1; sqv[u * 4 + 1] += t1 * t1;
                st[u * 4 + 2] += t2; sqv[u * 4 + 2] += t2 * t2;
                st[u * 4 + 3] += t3; sqv[u * 4 + 3] += t3 * t3;
            }
        }
    }
    #pragma unroll
    for (int dstep = 4; dstep <= 16; dstep <<= 1)
        #pragma unroll
        for (int k = 0; k < 16; k++) {
            st[k]  += __shfl_xor_sync(0xffffffffu, st[k],  dstep);
            sqv[k] += __shfl_xor_sync(0xffffffffu, sqv[k], dstep);
        }
    int lane = tid & 31;
    if (lane < 4) {
        #pragma unroll
        for (int k = 0; k < 16; k++) {
            atomicAdd(&ss[lane * 16 + k], st[k]);
            atomicAdd(&sq[lane * 16 + k], sqv[k]);
        }
    }
    __syncthreads();
    if (tid < 64) {
        atomicAdd(&g_s2[tid], (double)ss[tid]);
        atomicAdd(&g_q2[tid], (double)sq[tid]);
    }
}

// ---------------- 64-ch aggregate of t2*dis (warp-per-node, pure sum) -> a3 fp32 ----------------
__global__ void __launch_bounds__(256) k_agg64() {
    int n = (blockIdx.x * 256 + threadIdx.x) >> 5;
    int lane = threadIdx.x & 31;
    if (n >= NN) return;
    const __half2* t2p = g_h16;
    float dn = g_dis[n];
    float2 acc = __half22float2(t2p[n * 32 + lane]);
    int j = g_off[n], end = j + g_degi[n];
    for (; j + 8 <= end; j += 8) {
        int e[8];
        #pragma unroll
        for (int u = 0; u < 8; u++) e[u] = g_esrc[j + u];
        __half2 m[8];
        #pragma unroll
        for (int u = 0; u < 8; u++) m[u] = t2p[e[u] * 32 + lane];
        #pragma unroll
        for (int u = 0; u < 8; u++) {
            float2 mf = __half22float2(m[u]);
            acc.x += mf.x; acc.y += mf.y;
        }
    }
    for (; j < end; j++) {
        float2 m = __half22float2(t2p[g_esrc[j] * 32 + lane]);
        acc.x += m.x; acc.y += m.y;
    }
    ((float2*)g_hw)[n * 32 + lane] = make_float2(acc.x * dn, acc.y * dn);
}

// ---------------- layer 3 GEMM (BN2 folded across agg) + tanh + pool scatter ----------------
// Also restores g_degi = 0 (its last reader, k_agg64, has completed).
__global__ void __launch_bounds__(128) k_gemm3(const float* __restrict__ W3,
                                               const float* __restrict__ g2,
                                               const float* __restrict__ be2,
                                               const float* __restrict__ b3,
                                               const int* __restrict__ batch) {
    __shared__ float sS[64], sC[64], sWp[4096], sCB[64], sB[64];
    int tid = threadIdx.x;
    int T = blockIdx.x * blockDim.x + tid;
    if (T < NN) g_degi[T] = 0;        // restore invariant
    if (tid < 64) {
        float m = (float)(g_s2[tid] / (double)NN);
        float vv = (float)(g_q2[tid] / (double)NN) - m * m;
        float s = g2[tid] * rsqrtf(vv + EPSBN);
        sS[tid] = s;
        sC[tid] = be2[tid] - m * s;
        sB[tid] = b3[tid];
    }
    __syncthreads();
    for (int j = tid; j < 4096; j += blockDim.x) sWp[j] = W3[j] * sS[j >> 6];
    if (tid < 64) {
        float cb = 0.f;
        #pragma unroll
        for (int k = 0; k < 64; k++) cb += sC[k] * W3[k * 64 + tid];
        sCB[tid] = cb;
    }
    __syncthreads();
    if (T >= NN) return;
    int nq = T >> 2, oq = T & 3;
    int i0 = nq * 4;
    const float4* t4 = (const float4*)g_hw;     // a3 [N,64] fp32
    const float4* sWp4 = (const float4*)sWp;
    float4 acc[4][4];
    #pragma unroll
    for (int j = 0; j < 4; j++)
        #pragma unroll
        for (int u = 0; u < 4; u++) acc[j][u] = make_float4(0.f, 0.f, 0.f, 0.f);
    for (int kk = 0; kk < 16; kk++) {
        float4 tv[4];
        #pragma unroll
        for (int j = 0; j < 4; j++) tv[j] = t4[(i0 + j) * 16 + kk];
        #pragma unroll
        for (int jj = 0; jj < 4; jj++) {
            int k = kk * 4 + jj;
            float4 wv[4];
            #pragma unroll
            for (int u = 0; u < 4; u++) wv[u] = sWp4[k * 16 + oq * 4 + u];
            #pragma unroll
            for (int j = 0; j < 4; j++) {
                float xs = getc(tv[j], jj);
                #pragma unroll
                for (int u = 0; u < 4; u++) fma4(acc[j][u], wv[u], xs);
            }
        }
    }
    const float4* sCB4 = (const float4*)sCB;
    const float4* sB4 = (const float4*)sB;
    #pragma unroll
    for (int j = 0; j < 4; j++) {
        int i = i0 + j;
        float rs = g_rs[i];
        int gidx = batch[i];
        #pragma unroll
        for (int u = 0; u < 4; u++) {
            float4 cb = sCB4[oq * 4 + u];
            float4 bb = sB4[oq * 4 + u];
            float t0 = tanhf(fmaf(rs, cb.x, acc[j][u].x + bb.x));
            float t1 = tanhf(fmaf(rs, cb.y, acc[j][u].y + bb.y));
            float t2 = tanhf(fmaf(rs, cb.z, acc[j][u].z + bb.z));
            float t3 = tanhf(fmaf(rs, cb.w, acc[j][u].w + bb.w));
            red4(&g_pool[gidx * 64 + oq * 16 + u * 4], t0, t1, t2, t3);
        }
    }
}

// ---------------- head + restore accumulators to zero ----------------
__global__ void k_final(const float* __restrict__ Wc, const float* __restrict__ bc,
                        float* __restrict__ out) {
    __shared__ float sW[64];
    int g = threadIdx.x;
    if (g < 64) sW[g] = Wc[g];
    __syncthreads();
    float result = 0.f;
    if (g < GG) {
        float cnt = fmaxf(g_cnt[g], 1.f);
        float acc = 0.f;
        #pragma unroll
        for (int c = 0; c < 64; c++) acc += g_pool[g * 64 + c] * sW[c];
        result = acc / cnt + bc[0];
    }
    __syncthreads();                  // all reads of pool/cnt/stats done
    if (g < GG) out[g] = result;
    float4* p4 = (float4*)g_pool;
    for (int i = g; i < GG * 16; i += 512)
        p4[i] = make_float4(0.f, 0.f, 0.f, 0.f);
    if (g < GG) g_cnt[g] = 0.f;
    if (g < 16) { g_s1[g] = 0.0; g_q1[g] = 0.0; }
    if (g < 64) { g_s2[g] = 0.0; g_q2[g] = 0.0; }
}

// ---------------- launch ----------------
extern "C" void kernel_launch(void* const* d_in, const int* in_sizes, int n_in,
                              void* d_out, int out_size) {
    const float* x    = (const float*)d_in[0];
    const int*   ei   = (const int*)d_in[1];
    const int*   batch= (const int*)d_in[2];
    const float* W1   = (const float*)d_in[3];
    const float* b1   = (const float*)d_in[4];
    const float* g1   = (const float*)d_in[5];
    const float* be1  = (const float*)d_in[6];
    const float* W2   = (const float*)d_in[7];
    const float* b2   = (const float*)d_in[8];
    const float* g2   = (const float*)d_in[9];
    const float* be2  = (const float*)d_in[10];
    const float* W3   = (const float*)d_in[11];
    const float* b3   = (const float*)d_in[12];
    const float* Wc   = (const float*)d_in[13];
    const float* bc   = (const float*)d_in[14];
    float* out = (float*)d_out;

    k_deg        <<<FILL_BLOCKS, 256>>>(ei);
    k_scan       <<<(NN + 255) / 256, 256>>>(batch);
    k_fill_gemm1 <<<FILL_BLOCKS + G1_BLOCKS, 256>>>(ei, x, W1);

    k_agg16      <<<(NN + 63) / 64, 256>>>(b1);

    k_agg16b     <<<(NN + 63) / 64, 256>>>();
    k_gemm2      <<<(NN + 127) / 128, 128>>>(W2, g1, be1, b2);

    k_agg64      <<<(NN * 32 + 255) / 256, 256>>>();
    k_gemm3      <<<(NN + 127) / 128, 128>>>(W3, g2, be2, b3, batch);

    k_final      <<<1, 512>>>(Wc, bc, out);
}